// round 14
// baseline (speedup 1.0000x reference)
#include <cuda_runtime.h>
#include <cstdint>

#define T_STEPS 1024
#define BATCH   64
#define DIN     256
#define DH      256
#define G4      1024   // 4*DH
#define OUT_MAIN (T_STEPS*BATCH*DH)

// ---------------- scratch (static device globals; no allocation) ----------------
__device__ float g_Gx[(size_t)T_STEPS * BATCH * G4];   // precomputed x-part of gates
__device__ float g_Wxp[G4 * DIN];                      // packed Wx rows: [j][k]
__device__ float g_bvec[G4];                           // packed bias
__device__ float g_hT[2][16][DH][4];                   // double-buffered h, transposed, tf32
__device__ unsigned int g_flags[16 * 16];              // per-group: 8 producer flags

// ---------------- primitives ----------------
__device__ __forceinline__ void st_release(unsigned int* p, unsigned int v) {
    asm volatile("st.release.gpu.u32 [%0], %1;" :: "l"(p), "r"(v) : "memory");
}
__device__ __forceinline__ unsigned int ld_acquire(const unsigned int* p) {
    unsigned int v;
    asm volatile("ld.acquire.gpu.u32 %0, [%1];" : "=r"(v) : "l"(p) : "memory");
    return v;
}
__device__ __forceinline__ float4 ldcg4(const float4* p) {
    float4 v;
    asm volatile("ld.global.cg.v4.f32 {%0,%1,%2,%3}, [%4];"
                 : "=f"(v.x), "=f"(v.y), "=f"(v.z), "=f"(v.w) : "l"(p) : "memory");
    return v;
}
__device__ __forceinline__ uint32_t to_tf32(float f) {
    uint32_t r;
    asm("cvt.rna.tf32.f32 %0, %1;" : "=r"(r) : "f"(f));
    return r;
}
__device__ __forceinline__ void mma_tf32(float& d0, float& d1, float& d2, float& d3,
                                         uint32_t a0, uint32_t a1, uint32_t a2, uint32_t a3,
                                         uint32_t b0, uint32_t b1) {
    asm volatile("mma.sync.aligned.m16n8k8.row.col.f32.tf32.tf32.f32 "
                 "{%0,%1,%2,%3}, {%4,%5,%6,%7}, {%8,%9}, {%0,%1,%2,%3};"
                 : "+f"(d0), "+f"(d1), "+f"(d2), "+f"(d3)
                 : "r"(a0), "r"(a1), "r"(a2), "r"(a3), "r"(b0), "r"(b1));
}
__device__ __forceinline__ float sigm(float x) { return 1.f / (1.f + __expf(-x)); }
__device__ __forceinline__ float tanh_fast(float x) {
    float e = __expf(2.f * x);
    return (e - 1.f) * __frcp_rn(e + 1.f);
}

// ---------------- prep: pack Wx rows (j-major) + bias ----------------
__global__ void prep_kernel(const float* __restrict__ Wf, const float* __restrict__ Wi,
                            const float* __restrict__ Wg, const float* __restrict__ Wo,
                            const float* __restrict__ bF, const float* __restrict__ bI,
                            const float* __restrict__ bG, const float* __restrict__ bO)
{
    int idx = blockIdx.x * blockDim.x + threadIdx.x;
    const float* Ws[4] = {Wf, Wi, Wg, Wo};
    for (int i = idx; i < G4 * DIN; i += gridDim.x * blockDim.x) {
        int j = i >> 8;
        int k = i & 255;
        g_Wxp[i] = Ws[j >> 8][(j & 255) * 512 + k];
    }
    if (idx < G4) {
        int gate = idx >> 8, row = idx & 255;
        const float* bs[4] = {bF, bI, bG, bO};
        g_bvec[idx] = bs[gate][row];
    }
}

// ---------------- init: h0 -> transposed tf32 buffer 0, reset flags ----------------
__global__ void init_kernel(const float* __restrict__ h0)
{
    int i = blockIdx.x * blockDim.x + threadIdx.x;
    if (i < BATCH * DH) {
        int bb = i >> 8;
        int k  = i & 255;
        g_hT[0][bb >> 2][k][bb & 3] = __uint_as_float(to_tf32(h0[bb * DH + k]));
    }
    if (i < 16 * 16) g_flags[i] = 0;
}

// ---------------- phase 1: Gx = X @ Wx^T + b  -- tf32 tensor-core GEMM (R13) ----------------
__global__ __launch_bounds__(256) void gemm_x_kernel(const float* __restrict__ A)
{
    __shared__ float A_sm[128][36];
    __shared__ float B_sm[128][36];

    int tid  = threadIdx.x;
    int lane = tid & 31;
    int wid  = tid >> 5;
    int bn = blockIdx.x;
    int bm = blockIdx.y;
    int wm = (wid & 3) * 32;
    int wn = (wid >> 2) * 64;

    float acc[2][8][4];
    #pragma unroll
    for (int mi = 0; mi < 2; mi++)
        #pragma unroll
        for (int ni = 0; ni < 8; ni++)
            #pragma unroll
            for (int q = 0; q < 4; q++) acc[mi][ni][q] = 0.f;

    const float* Aptr = A + (size_t)bm * 128 * DIN;
    const float* Bptr = g_Wxp + (size_t)bn * 128 * DIN;

    int arow = tid >> 1;
    int koff = (tid & 1) * 16;

    for (int kb = 0; kb < 8; kb++) {
        int kbase = kb * 32;
        const float4* ap = (const float4*)(Aptr + arow * DIN + kbase + koff);
        const float4* bp = (const float4*)(Bptr + arow * DIN + kbase + koff);
        #pragma unroll
        for (int q = 0; q < 4; q++) {
            float4 av = ap[q];
            float4 bv = bp[q];
            int kk = koff + q * 4;
            A_sm[arow][kk + 0] = __uint_as_float(to_tf32(av.x));
            A_sm[arow][kk + 1] = __uint_as_float(to_tf32(av.y));
            A_sm[arow][kk + 2] = __uint_as_float(to_tf32(av.z));
            A_sm[arow][kk + 3] = __uint_as_float(to_tf32(av.w));
            B_sm[arow][kk + 0] = __uint_as_float(to_tf32(bv.x));
            B_sm[arow][kk + 1] = __uint_as_float(to_tf32(bv.y));
            B_sm[arow][kk + 2] = __uint_as_float(to_tf32(bv.z));
            B_sm[arow][kk + 3] = __uint_as_float(to_tf32(bv.w));
        }
        __syncthreads();

        #pragma unroll
        for (int kc = 0; kc < 32; kc += 8) {
            uint32_t af[2][4];
            #pragma unroll
            for (int mi = 0; mi < 2; mi++) {
                int r = wm + mi * 16 + (lane >> 2);
                af[mi][0] = __float_as_uint(A_sm[r][kc + (lane & 3)]);
                af[mi][1] = __float_as_uint(A_sm[r + 8][kc + (lane & 3)]);
                af[mi][2] = __float_as_uint(A_sm[r][kc + 4 + (lane & 3)]);
                af[mi][3] = __float_as_uint(A_sm[r + 8][kc + 4 + (lane & 3)]);
            }
            #pragma unroll
            for (int ni = 0; ni < 8; ni++) {
                int nr = wn + ni * 8 + (lane >> 2);
                uint32_t b0 = __float_as_uint(B_sm[nr][kc + (lane & 3)]);
                uint32_t b1 = __float_as_uint(B_sm[nr][kc + 4 + (lane & 3)]);
                #pragma unroll
                for (int mi = 0; mi < 2; mi++)
                    mma_tf32(acc[mi][ni][0], acc[mi][ni][1], acc[mi][ni][2], acc[mi][ni][3],
                             af[mi][0], af[mi][1], af[mi][2], af[mi][3], b0, b1);
            }
        }
        __syncthreads();
    }

    int r  = lane >> 2;
    int c2 = 2 * (lane & 3);
    #pragma unroll
    for (int ni = 0; ni < 8; ni++) {
        int j = bn * 128 + wn + ni * 8 + c2;
        float bb0 = g_bvec[j];
        float bb1 = g_bvec[j + 1];
        #pragma unroll
        for (int mi = 0; mi < 2; mi++) {
            size_t m0 = (size_t)bm * 128 + wm + mi * 16 + r;
            float* op  = g_Gx + m0 * G4 + j;
            float* op2 = g_Gx + (m0 + 8) * G4 + j;
            op[0]  = acc[mi][ni][0] + bb0;
            op[1]  = acc[mi][ni][1] + bb1;
            op2[0] = acc[mi][ni][2] + bb0;
            op2[1] = acc[mi][ni][3] + bb1;
        }
    }
}

// ---------------- phase 2: persistent recurrent kernel (tf32 MMA) ----------------
// R13 architecture + (a) 4 independent MMA accumulator chains (breaks the serial
// 32-deep HMMA dependency), (b) Gx prefetched one step ahead AFTER the stage bar
// (keeps slow DRAM loads out of the L1tex queue ahead of the flag poll).
__global__ __launch_bounds__(256, 1) void lstm_kernel(
    const float* __restrict__ Wf, const float* __restrict__ Wi,
    const float* __restrict__ Wg, const float* __restrict__ Wo,
    const float* __restrict__ c0, float* __restrict__ out, int out_size)
{
    __shared__ alignas(16) float4 hT_sm4[DH];     // staged hT: [256 k][4 batch]
    __shared__ float D_sm[128][9];                // gates [gate_row][batch], padded

    int tid  = threadIdx.x;
    int lane = tid & 31;
    int mt   = tid >> 5;
    int grp  = blockIdx.x >> 3;
    int cg   = blockIdx.x & 7;

    // ---- load A fragments (weights, tf32) once ----
    int row_off = lane >> 2;
    int colk    = lane & 3;
    int g_th    = row_off & 3;
    const float* Wsel = (g_th == 0) ? Wf : (g_th == 1) ? Wi : (g_th == 2) ? Wg : Wo;
    int hh0 = mt * 4 + (row_off >> 2);
    int hh1 = hh0 + 2;
    const float* p0 = Wsel + (cg * 32 + hh0) * 512 + 256;
    const float* p1 = Wsel + (cg * 32 + hh1) * 512 + 256;

    uint32_t wA[32][4];
    #pragma unroll
    for (int kt = 0; kt < 32; kt++) {
        int k0 = kt * 8;
        wA[kt][0] = to_tf32(p0[k0 + colk]);
        wA[kt][1] = to_tf32(p1[k0 + colk]);
        wA[kt][2] = to_tf32(p0[k0 + colk + 4]);
        wA[kt][3] = to_tf32(p1[k0 + colk + 4]);
    }

    // ---- cell ownership ----
    int bloc  = tid & 3;
    int hh    = tid >> 2;
    int bglob = grp * 4 + bloc;
    int hglob = cg * 32 + hh;
    float cval = (tid < 128) ? c0[bglob * DH + hglob] : 0.f;

    // ---- B-fragment smem index ----
    int bcol  = lane >> 2;
    bool bval = bcol < 4;
    int bidx  = (lane & 3) * 4 + (bval ? bcol : 0);

    unsigned int* flags = &g_flags[grp * 16];
    const float4* hT_src  = (const float4*)&g_hT[0][grp][0][0];
    const float4* hT_src1 = (const float4*)&g_hT[1][grp][0][0];
    float* hT_dst0 = &g_hT[0][grp][hglob][bloc];
    float* hT_dst1 = &g_hT[1][grp][hglob][bloc];
    const float* gbase = g_Gx + (size_t)bglob * G4 + hglob;

    // ---- prologue: prefetch Gx for t=0 ----
    float gx0 = 0.f, gx1 = 0.f, gx2 = 0.f, gx3 = 0.f;
    if (tid < 128) {
        gx0 = __ldcs(gbase);
        gx1 = __ldcs(gbase + 256);
        gx2 = __ldcs(gbase + 512);
        gx3 = __ldcs(gbase + 768);
    }

    #pragma unroll 1
    for (int t = 0; t < T_STEPS; t++) {
        // wait for all 8 producers of this group to publish h[t]
        if (tid < 8) {
            while (ld_acquire(&flags[tid]) < (unsigned)t) { }
        }
        __syncthreads();

        // stage hT[t] (256 k x 4 batch) into smem; .cg bypasses stale L1
        hT_sm4[tid] = ldcg4(((t & 1) ? hT_src1 : hT_src) + tid);
        __syncthreads();

        // prefetch Gx for step t+1 (in flight across MMA+cell+next wait; never
        // sits ahead of the next flag poll in the L1tex queue by completion time)
        float ngx0 = 0.f, ngx1 = 0.f, ngx2 = 0.f, ngx3 = 0.f;
        if (tid < 128) {
            int tn = (t + 1 < T_STEPS) ? t + 1 : t;
            const float* gp = gbase + (size_t)tn * (BATCH * G4);
            ngx0 = __ldcs(gp);
            ngx1 = __ldcs(gp + 256);
            ngx2 = __ldcs(gp + 512);
            ngx3 = __ldcs(gp + 768);
        }

        // tensor MMA: 32 k-steps split into 4 independent accumulator chains
        float dacc[4][4];
        #pragma unroll
        for (int c = 0; c < 4; c++)
            #pragma unroll
            for (int q = 0; q < 4; q++) dacc[c][q] = 0.f;

        const float* hTf = (const float*)hT_sm4;
        #pragma unroll
        for (int kt = 0; kt < 32; kt++) {
            uint32_t b0 = 0u, b1 = 0u;
            if (bval) {
                b0 = __float_as_uint(hTf[kt * 32 + bidx]);
                b1 = __float_as_uint(hTf[kt * 32 + 16 + bidx]);
            }
            int c = kt & 3;
            mma_tf32(dacc[c][0], dacc[c][1], dacc[c][2], dacc[c][3],
                     wA[kt][0], wA[kt][1], wA[kt][2], wA[kt][3], b0, b1);
        }
        float d0 = (dacc[0][0] + dacc[1][0]) + (dacc[2][0] + dacc[3][0]);
        float d1 = (dacc[0][1] + dacc[1][1]) + (dacc[2][1] + dacc[3][1]);
        float d2 = (dacc[0][2] + dacc[1][2]) + (dacc[2][2] + dacc[3][2]);
        float d3 = (dacc[0][3] + dacc[1][3]) + (dacc[2][3] + dacc[3][3]);

        // write D cols 0..3 (batches) to smem
        int r0 = mt * 16 + (lane >> 2);
        int cc = lane & 3;
        if (cc < 2) {
            D_sm[r0][2 * cc]         = d0;
            D_sm[r0][2 * cc + 1]     = d1;
            D_sm[r0 + 8][2 * cc]     = d2;
            D_sm[r0 + 8][2 * cc + 1] = d3;
        }
        __syncthreads();

        // cell update: thread (hh, bloc); gates at rows hh*4+g
        if (tid < 128) {
            float fg = sigm(D_sm[hh * 4 + 0][bloc] + gx0);
            float ig = sigm(D_sm[hh * 4 + 1][bloc] + gx1);
            float gg = tanh_fast(D_sm[hh * 4 + 2][bloc] + gx2);
            float og = sigm(D_sm[hh * 4 + 3][bloc] + gx3);
            cval = fg * cval + ig * gg;
            float hn = og * tanh_fast(cval);
            float hn_tf = __uint_as_float(to_tf32(hn));
            if ((t + 1) & 1) *hT_dst1 = hn_tf; else *hT_dst0 = hn_tf;
            int idx = bglob * DH + hglob;
            out[(size_t)t * (BATCH * DH) + idx] = hn;
            if (t == T_STEPS - 1 && out_size > OUT_MAIN) {
                out[(size_t)OUT_MAIN + idx] = hn;
                out[(size_t)OUT_MAIN + BATCH * DH + idx] = cval;
            }
        }
        gx0 = ngx0; gx1 = ngx1; gx2 = ngx2; gx3 = ngx3;
        __syncthreads();

        // publish: all this CTA's hT stores ordered before the flag (bar + release)
        if (tid == 0) st_release(&flags[cg], (unsigned)(t + 1));
    }
}

// ---------------- launch ----------------
extern "C" void kernel_launch(void* const* d_in, const int* in_sizes, int n_in,
                              void* d_out, int out_size)
{
    const float* inputs = (const float*)d_in[0];
    const float* h0     = (const float*)d_in[1];
    const float* c0     = (const float*)d_in[2];
    const float* Wf     = (const float*)d_in[3];
    const float* bF     = (const float*)d_in[4];
    const float* Wi     = (const float*)d_in[5];
    const float* bI     = (const float*)d_in[6];
    const float* Wg     = (const float*)d_in[7];
    const float* bG     = (const float*)d_in[8];
    const float* Wo     = (const float*)d_in[9];
    const float* bO     = (const float*)d_in[10];
    float* out = (float*)d_out;

    prep_kernel<<<256, 256>>>(Wf, Wi, Wg, Wo, bF, bI, bG, bO);
    init_kernel<<<64, 256>>>(h0);
    gemm_x_kernel<<<dim3(8, 512), 256>>>(inputs);
    lstm_kernel<<<128, 256>>>(Wf, Wi, Wg, Wo, c0, out, out_size);
}

// round 15
// speedup vs baseline: 1.3007x; 1.3007x over previous
#include <cuda_runtime.h>
#include <cstdint>

#define T_STEPS 1024
#define BATCH   64
#define DIN     256
#define DH      256
#define G4      1024   // 4*DH
#define OUT_MAIN (T_STEPS*BATCH*DH)

// ---------------- scratch (static device globals; no allocation) ----------------
__device__ float g_Gx[(size_t)T_STEPS * BATCH * G4];   // precomputed x-part of gates
__device__ float g_Wxp[G4 * DIN];                      // packed Wx rows: [j][k]
__device__ float g_bvec[G4];                           // packed bias
__device__ float g_hT[2][16][DH][4];                   // double-buffered h, transposed, tf32
__device__ unsigned int g_flags[16 * 16];              // per-group: 8 producer flags

// ---------------- primitives ----------------
__device__ __forceinline__ void st_release(unsigned int* p, unsigned int v) {
    asm volatile("st.release.gpu.u32 [%0], %1;" :: "l"(p), "r"(v) : "memory");
}
__device__ __forceinline__ unsigned int ld_acquire(const unsigned int* p) {
    unsigned int v;
    asm volatile("ld.acquire.gpu.u32 %0, [%1];" : "=r"(v) : "l"(p) : "memory");
    return v;
}
__device__ __forceinline__ float4 ldcg4(const float4* p) {
    float4 v;
    asm volatile("ld.global.cg.v4.f32 {%0,%1,%2,%3}, [%4];"
                 : "=f"(v.x), "=f"(v.y), "=f"(v.z), "=f"(v.w) : "l"(p) : "memory");
    return v;
}
__device__ __forceinline__ uint32_t to_tf32(float f) {
    uint32_t r;
    asm("cvt.rna.tf32.f32 %0, %1;" : "=r"(r) : "f"(f));
    return r;
}
__device__ __forceinline__ void mma_tf32(float& d0, float& d1, float& d2, float& d3,
                                         uint32_t a0, uint32_t a1, uint32_t a2, uint32_t a3,
                                         uint32_t b0, uint32_t b1) {
    asm volatile("mma.sync.aligned.m16n8k8.row.col.f32.tf32.tf32.f32 "
                 "{%0,%1,%2,%3}, {%4,%5,%6,%7}, {%8,%9}, {%0,%1,%2,%3};"
                 : "+f"(d0), "+f"(d1), "+f"(d2), "+f"(d3)
                 : "r"(a0), "r"(a1), "r"(a2), "r"(a3), "r"(b0), "r"(b1));
}
__device__ __forceinline__ float sigm(float x) { return 1.f / (1.f + __expf(-x)); }
__device__ __forceinline__ float tanh_fast(float x) {
    float e = __expf(2.f * x);
    return (e - 1.f) * __frcp_rn(e + 1.f);
}

// ---------------- prep: pack Wx rows (j-major) + bias ----------------
__global__ void prep_kernel(const float* __restrict__ Wf, const float* __restrict__ Wi,
                            const float* __restrict__ Wg, const float* __restrict__ Wo,
                            const float* __restrict__ bF, const float* __restrict__ bI,
                            const float* __restrict__ bG, const float* __restrict__ bO)
{
    int idx = blockIdx.x * blockDim.x + threadIdx.x;
    const float* Ws[4] = {Wf, Wi, Wg, Wo};
    for (int i = idx; i < G4 * DIN; i += gridDim.x * blockDim.x) {
        int j = i >> 8;
        int k = i & 255;
        g_Wxp[i] = Ws[j >> 8][(j & 255) * 512 + k];
    }
    if (idx < G4) {
        int gate = idx >> 8, row = idx & 255;
        const float* bs[4] = {bF, bI, bG, bO};
        g_bvec[idx] = bs[gate][row];
    }
}

// ---------------- init: h0 -> transposed tf32 buffer 0, reset flags ----------------
__global__ void init_kernel(const float* __restrict__ h0)
{
    int i = blockIdx.x * blockDim.x + threadIdx.x;
    if (i < BATCH * DH) {
        int bb = i >> 8;
        int k  = i & 255;
        g_hT[0][bb >> 2][k][bb & 3] = __uint_as_float(to_tf32(h0[bb * DH + k]));
    }
    if (i < 16 * 16) g_flags[i] = 0;
}

// ---------------- phase 1: Gx = X @ Wx^T + b  -- tf32 tensor-core GEMM (R13) ----------------
__global__ __launch_bounds__(256) void gemm_x_kernel(const float* __restrict__ A)
{
    __shared__ float A_sm[128][36];
    __shared__ float B_sm[128][36];

    int tid  = threadIdx.x;
    int lane = tid & 31;
    int wid  = tid >> 5;
    int bn = blockIdx.x;
    int bm = blockIdx.y;
    int wm = (wid & 3) * 32;
    int wn = (wid >> 2) * 64;

    float acc[2][8][4];
    #pragma unroll
    for (int mi = 0; mi < 2; mi++)
        #pragma unroll
        for (int ni = 0; ni < 8; ni++)
            #pragma unroll
            for (int q = 0; q < 4; q++) acc[mi][ni][q] = 0.f;

    const float* Aptr = A + (size_t)bm * 128 * DIN;
    const float* Bptr = g_Wxp + (size_t)bn * 128 * DIN;

    int arow = tid >> 1;
    int koff = (tid & 1) * 16;

    for (int kb = 0; kb < 8; kb++) {
        int kbase = kb * 32;
        const float4* ap = (const float4*)(Aptr + arow * DIN + kbase + koff);
        const float4* bp = (const float4*)(Bptr + arow * DIN + kbase + koff);
        #pragma unroll
        for (int q = 0; q < 4; q++) {
            float4 av = ap[q];
            float4 bv = bp[q];
            int kk = koff + q * 4;
            A_sm[arow][kk + 0] = __uint_as_float(to_tf32(av.x));
            A_sm[arow][kk + 1] = __uint_as_float(to_tf32(av.y));
            A_sm[arow][kk + 2] = __uint_as_float(to_tf32(av.z));
            A_sm[arow][kk + 3] = __uint_as_float(to_tf32(av.w));
            B_sm[arow][kk + 0] = __uint_as_float(to_tf32(bv.x));
            B_sm[arow][kk + 1] = __uint_as_float(to_tf32(bv.y));
            B_sm[arow][kk + 2] = __uint_as_float(to_tf32(bv.z));
            B_sm[arow][kk + 3] = __uint_as_float(to_tf32(bv.w));
        }
        __syncthreads();

        #pragma unroll
        for (int kc = 0; kc < 32; kc += 8) {
            uint32_t af[2][4];
            #pragma unroll
            for (int mi = 0; mi < 2; mi++) {
                int r = wm + mi * 16 + (lane >> 2);
                af[mi][0] = __float_as_uint(A_sm[r][kc + (lane & 3)]);
                af[mi][1] = __float_as_uint(A_sm[r + 8][kc + (lane & 3)]);
                af[mi][2] = __float_as_uint(A_sm[r][kc + 4 + (lane & 3)]);
                af[mi][3] = __float_as_uint(A_sm[r + 8][kc + 4 + (lane & 3)]);
            }
            #pragma unroll
            for (int ni = 0; ni < 8; ni++) {
                int nr = wn + ni * 8 + (lane >> 2);
                uint32_t b0 = __float_as_uint(B_sm[nr][kc + (lane & 3)]);
                uint32_t b1 = __float_as_uint(B_sm[nr][kc + 4 + (lane & 3)]);
                #pragma unroll
                for (int mi = 0; mi < 2; mi++)
                    mma_tf32(acc[mi][ni][0], acc[mi][ni][1], acc[mi][ni][2], acc[mi][ni][3],
                             af[mi][0], af[mi][1], af[mi][2], af[mi][3], b0, b1);
            }
        }
        __syncthreads();
    }

    int r  = lane >> 2;
    int c2 = 2 * (lane & 3);
    #pragma unroll
    for (int ni = 0; ni < 8; ni++) {
        int j = bn * 128 + wn + ni * 8 + c2;
        float bb0 = g_bvec[j];
        float bb1 = g_bvec[j + 1];
        #pragma unroll
        for (int mi = 0; mi < 2; mi++) {
            size_t m0 = (size_t)bm * 128 + wm + mi * 16 + r;
            float* op  = g_Gx + m0 * G4 + j;
            float* op2 = g_Gx + (m0 + 8) * G4 + j;
            op[0]  = acc[mi][ni][0] + bb0;
            op[1]  = acc[mi][ni][1] + bb1;
            op2[0] = acc[mi][ni][2] + bb0;
            op2[1] = acc[mi][ni][3] + bb1;
        }
    }
}

// ---------------- phase 2: persistent recurrent kernel (tf32 MMA) ----------------
// Exact R13 structure (Gx prefetch BEFORE the wait, consumed same iteration) with ONE
// change: the 32 chained MMAs are split into 4 independent accumulator chains
// (depth 32 -> 8) and summed at the end.
__global__ __launch_bounds__(256, 1) void lstm_kernel(
    const float* __restrict__ Wf, const float* __restrict__ Wi,
    const float* __restrict__ Wg, const float* __restrict__ Wo,
    const float* __restrict__ c0, float* __restrict__ out, int out_size)
{
    __shared__ alignas(16) float4 hT_sm4[DH];     // staged hT: [256 k][4 batch]
    __shared__ float D_sm[128][9];                // gates [gate_row][batch], padded

    int tid  = threadIdx.x;
    int lane = tid & 31;
    int mt   = tid >> 5;          // warp = m-tile 0..7
    int grp  = blockIdx.x >> 3;   // batch group 0..15
    int cg   = blockIdx.x & 7;    // h-slice 0..7

    // ---- load A fragments (weights, tf32) once ----
    int row_off = lane >> 2;
    int colk    = lane & 3;
    int g_th    = row_off & 3;
    const float* Wsel = (g_th == 0) ? Wf : (g_th == 1) ? Wi : (g_th == 2) ? Wg : Wo;
    int hh0 = mt * 4 + (row_off >> 2);
    int hh1 = hh0 + 2;
    const float* p0 = Wsel + (cg * 32 + hh0) * 512 + 256;
    const float* p1 = Wsel + (cg * 32 + hh1) * 512 + 256;

    uint32_t wA[32][4];
    #pragma unroll
    for (int kt = 0; kt < 32; kt++) {
        int k0 = kt * 8;
        wA[kt][0] = to_tf32(p0[k0 + colk]);
        wA[kt][1] = to_tf32(p1[k0 + colk]);
        wA[kt][2] = to_tf32(p0[k0 + colk + 4]);
        wA[kt][3] = to_tf32(p1[k0 + colk + 4]);
    }

    // ---- cell ownership: tid<128, batch = tid&3, h col = tid>>2 ----
    int bloc  = tid & 3;
    int hh    = tid >> 2;
    int bglob = grp * 4 + bloc;
    int hglob = cg * 32 + hh;
    float cval = (tid < 128) ? c0[bglob * DH + hglob] : 0.f;

    // ---- B-fragment smem index (conflict-free) ----
    int bcol  = lane >> 2;
    bool bval = bcol < 4;
    int bidx  = (lane & 3) * 4 + (bval ? bcol : 0);

    unsigned int* flags = &g_flags[grp * 16];
    const float4* hT_src  = (const float4*)&g_hT[0][grp][0][0];
    const float4* hT_src1 = (const float4*)&g_hT[1][grp][0][0];
    float* hT_dst0 = &g_hT[0][grp][hglob][bloc];
    float* hT_dst1 = &g_hT[1][grp][hglob][bloc];

    #pragma unroll 1
    for (int t = 0; t < T_STEPS; t++) {
        // prefetch Gx for this step (issued BEFORE the wait; latency hidden by the wait)
        float gx0, gx1, gx2, gx3;
        if (tid < 128) {
            const float* gp = g_Gx + (size_t)t * (BATCH * G4) + (size_t)bglob * G4 + hglob;
            gx0 = __ldcs(gp);
            gx1 = __ldcs(gp + 256);
            gx2 = __ldcs(gp + 512);
            gx3 = __ldcs(gp + 768);
        }

        // wait for all 8 producers of this group to publish h[t]
        if (tid < 8) {
            while (ld_acquire(&flags[tid]) < (unsigned)t) { }
        }
        __syncthreads();

        // stage hT[t] (256 k x 4 batch) into smem; .cg bypasses stale L1
        hT_sm4[tid] = ldcg4(((t & 1) ? hT_src1 : hT_src) + tid);
        __syncthreads();

        // tensor MMA: 32 k-steps in 4 independent accumulator chains (depth 8)
        float dacc[4][4];
        #pragma unroll
        for (int c = 0; c < 4; c++)
            #pragma unroll
            for (int q = 0; q < 4; q++) dacc[c][q] = 0.f;

        const float* hTf = (const float*)hT_sm4;
        #pragma unroll
        for (int kt = 0; kt < 32; kt++) {
            uint32_t b0 = 0u, b1 = 0u;
            if (bval) {
                b0 = __float_as_uint(hTf[kt * 32 + bidx]);
                b1 = __float_as_uint(hTf[kt * 32 + 16 + bidx]);
            }
            int c = kt & 3;
            mma_tf32(dacc[c][0], dacc[c][1], dacc[c][2], dacc[c][3],
                     wA[kt][0], wA[kt][1], wA[kt][2], wA[kt][3], b0, b1);
        }
        float d0 = (dacc[0][0] + dacc[1][0]) + (dacc[2][0] + dacc[3][0]);
        float d1 = (dacc[0][1] + dacc[1][1]) + (dacc[2][1] + dacc[3][1]);
        float d2 = (dacc[0][2] + dacc[1][2]) + (dacc[2][2] + dacc[3][2]);
        float d3 = (dacc[0][3] + dacc[1][3]) + (dacc[2][3] + dacc[3][3]);

        // write D cols 0..3 (batches) to smem
        int r0 = mt * 16 + (lane >> 2);
        int cc = lane & 3;
        if (cc < 2) {
            D_sm[r0][2 * cc]         = d0;
            D_sm[r0][2 * cc + 1]     = d1;
            D_sm[r0 + 8][2 * cc]     = d2;
            D_sm[r0 + 8][2 * cc + 1] = d3;
        }
        __syncthreads();

        // cell update: thread (hh, bloc); gates at rows hh*4+g
        if (tid < 128) {
            float fg = sigm(D_sm[hh * 4 + 0][bloc] + gx0);
            float ig = sigm(D_sm[hh * 4 + 1][bloc] + gx1);
            float gg = tanh_fast(D_sm[hh * 4 + 2][bloc] + gx2);
            float og = sigm(D_sm[hh * 4 + 3][bloc] + gx3);
            cval = fg * cval + ig * gg;
            float hn = og * tanh_fast(cval);
            float hn_tf = __uint_as_float(to_tf32(hn));
            if ((t + 1) & 1) *hT_dst1 = hn_tf; else *hT_dst0 = hn_tf;
            int idx = bglob * DH + hglob;
            out[(size_t)t * (BATCH * DH) + idx] = hn;
            if (t == T_STEPS - 1 && out_size > OUT_MAIN) {
                out[(size_t)OUT_MAIN + idx] = hn;
                out[(size_t)OUT_MAIN + BATCH * DH + idx] = cval;
            }
        }
        __syncthreads();

        // publish: all this CTA's hT stores ordered before the flag (bar + release)
        if (tid == 0) st_release(&flags[cg], (unsigned)(t + 1));
    }
}

// ---------------- launch ----------------
extern "C" void kernel_launch(void* const* d_in, const int* in_sizes, int n_in,
                              void* d_out, int out_size)
{
    const float* inputs = (const float*)d_in[0];
    const float* h0     = (const float*)d_in[1];
    const float* c0     = (const float*)d_in[2];
    const float* Wf     = (const float*)d_in[3];
    const float* bF     = (const float*)d_in[4];
    const float* Wi     = (const float*)d_in[5];
    const float* bI     = (const float*)d_in[6];
    const float* Wg     = (const float*)d_in[7];
    const float* bG     = (const float*)d_in[8];
    const float* Wo     = (const float*)d_in[9];
    const float* bO     = (const float*)d_in[10];
    float* out = (float*)d_out;

    prep_kernel<<<256, 256>>>(Wf, Wi, Wg, Wo, bF, bI, bG, bO);
    init_kernel<<<64, 256>>>(h0);
    gemm_x_kernel<<<dim3(8, 512), 256>>>(inputs);
    lstm_kernel<<<128, 256>>>(Wf, Wi, Wg, Wo, c0, out, out_size);
}